// round 3
// baseline (speedup 1.0000x reference)
#include <cuda_runtime.h>

#define EPS 1e-5f

typedef unsigned long long u64;

// ---------------- f32x2 helpers ----------------
__device__ __forceinline__ void fma2(u64& d, u64 a, u64 b) {
    asm volatile("fma.rn.f32x2 %0, %1, %2, %0;" : "+l"(d) : "l"(a), "l"(b));
}
__device__ __forceinline__ u64 dup2(float x) {
    u64 r; asm("mov.b64 %0, {%1, %1};" : "=l"(r) : "f"(x)); return r;
}
__device__ __forceinline__ float2 unpack2(u64 v) {
    float2 r; asm("mov.b64 {%0, %1}, %2;" : "=f"(r.x), "=f"(r.y) : "l"(v)); return r;
}

// ---------------- scratch (device globals; no allocation allowed) ----------------
__device__ float g_invn[16384];               // per-position 1/||x||
__device__ float g_wint[144 * 64];            // w_in transposed [c][o]
__device__ float g_w1tt[9 * 64 * 64];         // w1 as [drds][o2][o]
__device__ float g_w2tt[64 * 576];            // w2 as [o3][rs*64+o2]
__device__ float g_sin[64], g_tin[64];
__device__ float g_s1[64],  g_t1[64];
__device__ float g_s2[64],  g_t2[64];
__device__ float g_sout[144], g_tout[144];
__device__ float g_A[16384 * 25 * 64];        // post GEMM1+BN+ReLU  [pos][k][o]
__device__ float g_A1[16384 * 9 * 64];        // post conv1+BN+ReLU  [pos][rs][o2]
__device__ float g_B2[16384 * 64];            // post conv2+BN+ReLU  [pos][o3]

// ---------------- weight transpose + BN folding ----------------
__global__ void prep_kernel(const float* __restrict__ w_in,
                            const float* __restrict__ gin, const float* __restrict__ bin,
                            const float* __restrict__ min_, const float* __restrict__ vin,
                            const float* __restrict__ w1,
                            const float* __restrict__ g1, const float* __restrict__ b1,
                            const float* __restrict__ m1, const float* __restrict__ v1,
                            const float* __restrict__ w2,
                            const float* __restrict__ g2, const float* __restrict__ b2,
                            const float* __restrict__ m2, const float* __restrict__ v2,
                            const float* __restrict__ go, const float* __restrict__ bo,
                            const float* __restrict__ mo, const float* __restrict__ vo)
{
    int i = blockIdx.x * blockDim.x + threadIdx.x;   // grid covers 36864
    if (i < 36864) {
        // w1tt[drds][o2][o] = w1[o2][o][drds]
        int drds = i >> 12; int r1 = i & 4095;
        int o2 = r1 >> 6; int o = r1 & 63;
        g_w1tt[i] = w1[(o2 * 64 + o) * 9 + drds];
        // w2tt[o3][rs*64+o2] = w2[o3][o2][rs]
        int o3 = i / 576; int r2 = i - o3 * 576;
        int rs = r2 >> 6; int o2b = r2 & 63;
        g_w2tt[i] = w2[(o3 * 64 + o2b) * 9 + rs];
    }
    if (i < 9216) { int c = i >> 6; int o = i & 63; g_wint[i] = w_in[o * 144 + c]; }
    if (i < 64) {
        float s;
        s = gin[i] * rsqrtf(vin[i] + EPS); g_sin[i] = s; g_tin[i] = bin[i] - min_[i] * s;
        s = g1[i]  * rsqrtf(v1[i]  + EPS); g_s1[i]  = s; g_t1[i]  = b1[i]  - m1[i]  * s;
        s = g2[i]  * rsqrtf(v2[i]  + EPS); g_s2[i]  = s; g_t2[i]  = b2[i]  - m2[i]  * s;
    }
    if (i < 144) {
        float s = go[i] * rsqrtf(vo[i] + EPS); g_sout[i] = s; g_tout[i] = bo[i] - mo[i] * s;
    }
}

// ---------------- inverse L2 norm per position ----------------
__global__ void invn_kernel(const float* __restrict__ x)
{
    int p = blockIdx.x * 256 + threadIdx.x;          // 16384 positions
    int b = p >> 12, hw = p & 4095;
    const float* xb = x + (size_t)b * 589824 + hw;   // 144*4096
    float ss = 0.f;
    #pragma unroll 4
    for (int c = 0; c < 144; c++) { float v = xb[c * 4096]; ss += v * v; }
    g_invn[p] = 1.0f / fmaxf(sqrtf(ss), 1e-12f);
}

// ---------------- GEMM1: z[p,k,o] = sum_c w_in[o,c]*y[c,k,p]; BN+ReLU ----------------
// CTA = 8 positions. smem: y[144][25][8] + xc[144][8] + sc[25][8] = 120.6KB -> 1 CTA/SM.
// Half-warp scheme: lanes 0-15 own p-pairs {0,1}, lanes 16-31 own {2,3};
// each thread 4 output channels (oc, +16, +32, +48). f32x2 packed along p.
__global__ void __launch_bounds__(256) gemm1_kernel(const float* __restrict__ x)
{
    extern __shared__ float sm[];
    float* y  = sm;                                  // 28800
    float* xc = sm + 28800;                          // 1152
    float* sc = sm + 29952;                          // 200
    int pos0 = blockIdx.x << 3;
    int b = pos0 >> 12, hw0 = pos0 & 4095;
    int h = hw0 >> 6, w0 = hw0 & 63;
    int tid = threadIdx.x;
    const float* xb = x + (size_t)b * 589824;

    // stage 1: raw center values + combined norm scales
    for (int idx = tid; idx < 1152; idx += 256) {
        int c = idx >> 3, p = idx & 7;
        xc[idx] = xb[c * 4096 + (h << 6) + w0 + p];
    }
    if (tid < 200) {
        int k = tid >> 3, p = tid & 7;
        int kh = k / 5, kw = k - kh * 5;
        int gh = h + kh - 2, gw = w0 + p + kw - 2;
        float s = 0.f;
        if ((unsigned)gh < 64u && (unsigned)gw < 64u)
            s = g_invn[(b << 12) + (gh << 6) + gw] * g_invn[(b << 12) + (h << 6) + w0 + p];
        sc[tid] = s;
    }
    __syncthreads();

    // stage 2: build y[c][k][8p] = x_patch * x_ctr * sc
    for (int u = tid; u < 3600; u += 256) {
        int c = u / 25, k = u - c * 25;
        int kh = k / 5, kw = k - kh * 5;
        int ghc = min(max(h + kh - 2, 0), 63);
        const float* xr = xb + c * 4096 + (ghc << 6);
        int gw0 = w0 + kw - 2;
        float v[8];
        #pragma unroll
        for (int p = 0; p < 8; p++) {
            int gwc = min(max(gw0 + p, 0), 63);
            v[p] = xr[gwc] * xc[(c << 3) + p] * sc[(k << 3) + p];
        }
        float* yo = y + (u << 3);
        ((float4*)yo)[0] = make_float4(v[0], v[1], v[2], v[3]);
        ((float4*)yo)[1] = make_float4(v[4], v[5], v[6], v[7]);
    }
    __syncthreads();

    int lane = tid & 31, g = tid >> 5;
    int oc = lane & 15, hw = lane >> 4;
    int nk = (g == 0) ? 4 : 3;                       // k = g + 8*kk
    u64 acc[4][4][2];                                // [kk][ch][pair]
    #pragma unroll
    for (int kk = 0; kk < 4; kk++)
        #pragma unroll
        for (int j = 0; j < 4; j++) { acc[kk][j][0] = 0; acc[kk][j][1] = 0; }

    for (int c = 0; c < 144; c++) {
        u64 wd[4];
        #pragma unroll
        for (int j = 0; j < 4; j++) wd[j] = dup2(g_wint[(c << 6) + oc + (j << 4)]);
        #pragma unroll
        for (int kk = 0; kk < 4; kk++) {
            if (kk < nk) {
                int k = g + (kk << 3);
                ulonglong2 yv = *(const ulonglong2*)&y[((c * 25 + k) << 3) + (hw << 2)];
                #pragma unroll
                for (int j = 0; j < 4; j++) {
                    fma2(acc[kk][j][0], yv.x, wd[j]);
                    fma2(acc[kk][j][1], yv.y, wd[j]);
                }
            }
        }
    }

    #pragma unroll
    for (int kk = 0; kk < 4; kk++) {
        if (kk < nk) {
            int k = g + (kk << 3);
            #pragma unroll
            for (int j = 0; j < 4; j++) {
                int o = oc + (j << 4);
                float s = g_sin[o], t = g_tin[o];
                #pragma unroll
                for (int q = 0; q < 2; q++) {
                    float2 v = unpack2(acc[kk][j][q]);
                    int p0 = (hw << 2) + (q << 1);
                    g_A[(((pos0 + p0)     * 25 + k) << 6) + o] = fmaxf(v.x * s + t, 0.f);
                    g_A[(((pos0 + p0 + 1) * 25 + k) << 6) + o] = fmaxf(v.y * s + t, 0.f);
                }
            }
        }
    }
}

// ---------------- Conv1: 3x3 VALID over 5x5 grid, 64->64; BN+ReLU ----------------
// CTA = 16 positions. smem: A[16][25][64] (100KB) + w slice [64][68] (17KB) -> 1 CTA/SM.
// Half-warp hwid = g*2 + (lane>>4) owns position hwid, all 9 rs units;
// each thread 4 channels (oc, +16, +32, +48). f32x2 along contraction o, LDS.128.
__global__ void __launch_bounds__(256) conv1_kernel()
{
    extern __shared__ float sm[];
    float* As  = sm;                                 // 25600
    float* ws1 = sm + 25600;                         // 64*68 = 4352
    int pos0 = blockIdx.x << 4;
    int tid = threadIdx.x;

    const float4* Ag = (const float4*)(g_A + ((size_t)pos0 * 1600));
    for (int i = tid; i < 6400; i += 256) ((float4*)As)[i] = Ag[i];

    int lane = tid & 31, g = tid >> 5;
    int oc = lane & 15;
    int hwid = (g << 1) + (lane >> 4);               // position within CTA
    int abase = hwid * 1600;

    u64 acc[9][4];                                   // [rs][ch]
    #pragma unroll
    for (int i = 0; i < 9; i++)
        #pragma unroll
        for (int j = 0; j < 4; j++) acc[i][j] = 0;

    for (int drds = 0; drds < 9; drds++) {
        __syncthreads();                             // As ready (iter0) / ws1 drained
        const float* wsrc = g_w1tt + (drds << 12);
        #pragma unroll
        for (int j2 = 0; j2 < 16; j2++) {
            int idx = tid + (j2 << 8);
            ws1[(idx >> 6) * 68 + (idx & 63)] = wsrc[idx];
        }
        __syncthreads();

        int dr = drds / 3, ds = drds - dr * 3;
        int shift = dr * 5 + ds;
        int base[9];
        #pragma unroll
        for (int i = 0; i < 9; i++) {
            int r = i / 3, s = i - r * 3;
            base[i] = abase + ((r * 5 + s + shift) << 6);
        }

        for (int o = 0; o < 64; o += 4) {
            ulonglong2 wv[4];
            #pragma unroll
            for (int j = 0; j < 4; j++)
                wv[j] = *(const ulonglong2*)&ws1[(oc + (j << 4)) * 68 + o];
            #pragma unroll
            for (int i = 0; i < 9; i++) {
                ulonglong2 a = *(const ulonglong2*)&As[base[i] + o];
                #pragma unroll
                for (int j = 0; j < 4; j++) {
                    fma2(acc[i][j], a.x, wv[j].x);
                    fma2(acc[i][j], a.y, wv[j].y);
                }
            }
        }
    }

    #pragma unroll
    for (int i = 0; i < 9; i++) {
        int obase = ((pos0 + hwid) * 9 + i) << 6;
        #pragma unroll
        for (int j = 0; j < 4; j++) {
            int o = oc + (j << 4);
            float2 v = unpack2(acc[i][j]);
            g_A1[obase + o] = fmaxf((v.x + v.y) * g_s1[o] + g_t1[o], 0.f);
        }
    }
}

// ---------------- Conv2: 3x3 -> 1x1, 64->64; BN+ReLU ----------------
// CTA = 32 positions. smem: A1[32][576] (73.7KB) + w chunk [64][68] (17.4KB) -> 2 CTA/SM.
// f32x2 along contraction j, LDS.128 chunks of 4.
__global__ void __launch_bounds__(256) conv2_kernel()
{
    extern __shared__ float sm[];
    float* A1s = sm;                                 // 18432
    float* ws2 = sm + 18432;                         // 4352
    int pos0 = blockIdx.x << 5;
    int tid = threadIdx.x;

    const float4* src = (const float4*)(g_A1 + ((size_t)pos0 * 576));
    for (int i = tid; i < 4608; i += 256) ((float4*)A1s)[i] = src[i];

    int o3b = tid & 31, g = tid >> 5;                // warp g owns p = g+8i
    u64 acc[4][2];
    #pragma unroll
    for (int i = 0; i < 4; i++) { acc[i][0] = 0; acc[i][1] = 0; }

    for (int jc = 0; jc < 9; jc++) {
        __syncthreads();
        #pragma unroll
        for (int j2 = 0; j2 < 16; j2++) {
            int idx = tid + (j2 << 8);
            ws2[(idx >> 6) * 68 + (idx & 63)] = g_w2tt[(idx >> 6) * 576 + (jc << 6) + (idx & 63)];
        }
        __syncthreads();

        int jbase = jc << 6;
        for (int jj = 0; jj < 64; jj += 4) {
            ulonglong2 wlo = *(const ulonglong2*)&ws2[o3b * 68 + jj];
            ulonglong2 whi = *(const ulonglong2*)&ws2[(o3b + 32) * 68 + jj];
            #pragma unroll
            for (int i = 0; i < 4; i++) {
                int p = g + (i << 3);
                ulonglong2 a = *(const ulonglong2*)&A1s[p * 576 + jbase + jj];
                fma2(acc[i][0], a.x, wlo.x);
                fma2(acc[i][0], a.y, wlo.y);
                fma2(acc[i][1], a.x, whi.x);
                fma2(acc[i][1], a.y, whi.y);
            }
        }
    }

    float sa = g_s2[o3b], ta = g_t2[o3b], sb = g_s2[o3b + 32], tb = g_t2[o3b + 32];
    #pragma unroll
    for (int i = 0; i < 4; i++) {
        int p = pos0 + g + (i << 3);
        float2 va = unpack2(acc[i][0]);
        float2 vb = unpack2(acc[i][1]);
        g_B2[(p << 6) + o3b]      = fmaxf((va.x + va.y) * sa + ta, 0.f);
        g_B2[(p << 6) + o3b + 32] = fmaxf((vb.x + vb.y) * sb + tb, 0.f);
    }
}

// ---------------- GEMM out: 64->144, BN (no ReLU) ----------------
// CTA = 64 positions. f32x2 packed along output channels; broadcast LDS.128 weights.
__global__ void __launch_bounds__(256) gemmout_kernel(const float* __restrict__ w_out,
                                                      float* __restrict__ out)
{
    extern __shared__ float sm[];                    // 4160 + 9216 floats
    float* B2t = sm;
    float* ws  = sm + 4160;
    int pos0 = blockIdx.x << 6;
    int tid = threadIdx.x;

    for (int idx = tid; idx < 4096; idx += 256) {
        int p = idx >> 6, cm = idx & 63;
        B2t[cm * 65 + p] = g_B2[(pos0 << 6) + idx];
    }
    for (int idx = tid; idx < 9216; idx += 256) {
        int oc = idx >> 6, cm = idx & 63;
        ws[cm * 144 + oc] = w_out[idx];              // w_out[oc][cm]
    }
    __syncthreads();

    int pl = tid & 63, ocg = tid >> 6;               // ocg block of 36 oc
    u64 acc[18];
    #pragma unroll
    for (int j = 0; j < 18; j++) acc[j] = 0;

    for (int cm = 0; cm < 64; cm++) {
        u64 bv = dup2(B2t[cm * 65 + pl]);
        const ulonglong2* wp = (const ulonglong2*)&ws[cm * 144 + ocg * 36];
        #pragma unroll
        for (int j = 0; j < 9; j++) {
            ulonglong2 w = wp[j];
            fma2(acc[2 * j],     w.x, bv);
            fma2(acc[2 * j + 1], w.y, bv);
        }
    }

    int b = pos0 >> 12, hw0 = pos0 & 4095;
    float* op = out + (size_t)b * 589824 + hw0 + pl;
    #pragma unroll
    for (int j = 0; j < 18; j++) {
        int oc0 = ocg * 36 + 2 * j;
        float2 v = unpack2(acc[j]);
        op[(size_t)oc0 * 4096]       = v.x * g_sout[oc0]     + g_tout[oc0];
        op[(size_t)(oc0 + 1) * 4096] = v.y * g_sout[oc0 + 1] + g_tout[oc0 + 1];
    }
}

// ---------------- launch ----------------
extern "C" void kernel_launch(void* const* d_in, const int* in_sizes, int n_in,
                              void* d_out, int out_size)
{
    (void)in_sizes; (void)n_in; (void)out_size;
    const float* x     = (const float*)d_in[0];
    const float* w_in  = (const float*)d_in[1];
    const float* gin   = (const float*)d_in[2];
    const float* bin   = (const float*)d_in[3];
    const float* min_  = (const float*)d_in[4];
    const float* vin   = (const float*)d_in[5];
    const float* w1    = (const float*)d_in[6];
    const float* g1    = (const float*)d_in[7];
    const float* b1    = (const float*)d_in[8];
    const float* m1    = (const float*)d_in[9];
    const float* v1    = (const float*)d_in[10];
    const float* w2    = (const float*)d_in[11];
    const float* g2    = (const float*)d_in[12];
    const float* b2    = (const float*)d_in[13];
    const float* m2    = (const float*)d_in[14];
    const float* v2    = (const float*)d_in[15];
    const float* w_out = (const float*)d_in[16];
    const float* go    = (const float*)d_in[17];
    const float* bo    = (const float*)d_in[18];
    const float* mo    = (const float*)d_in[19];
    const float* vo    = (const float*)d_in[20];
    float* out = (float*)d_out;

    cudaFuncSetAttribute(gemm1_kernel,   cudaFuncAttributeMaxDynamicSharedMemorySize, 120608);
    cudaFuncSetAttribute(conv1_kernel,   cudaFuncAttributeMaxDynamicSharedMemorySize, 119808);
    cudaFuncSetAttribute(conv2_kernel,   cudaFuncAttributeMaxDynamicSharedMemorySize, 91136);
    cudaFuncSetAttribute(gemmout_kernel, cudaFuncAttributeMaxDynamicSharedMemorySize, 53504);

    prep_kernel<<<144, 256>>>(w_in, gin, bin, min_, vin,
                              w1, g1, b1, m1, v1,
                              w2, g2, b2, m2, v2,
                              go, bo, mo, vo);
    invn_kernel<<<64, 256>>>(x);
    gemm1_kernel<<<2048, 256, 120608>>>(x);
    conv1_kernel<<<1024, 256, 119808>>>();
    conv2_kernel<<<512, 256, 91136>>>();
    gemmout_kernel<<<256, 256, 53504>>>(w_out, out);
}